// round 1
// baseline (speedup 1.0000x reference)
#include <cuda_runtime.h>
#include <math.h>

#define NPTS 65536
#define GD   64
#define G3   (GD*GD*GD)
#define KNN  12

// ---------------- scratch (device globals; no allocation allowed) ----------------
__device__ float4   g_pts[NPTS];            // x,y,z,|x|^2
__device__ float    g_ff[NPTS*48];
__device__ float    g_h0[NPTS*256];
__device__ float    g_ga[NPTS*192];
__device__ float    g_gb[NPTS*192];
__device__ float    g_agg[NPTS*192];
__device__ float    g_ha[NPTS*256];
__device__ float    g_hb[NPTS*256];
__device__ int      g_knn[NPTS*KNN];
__device__ int      g_cellcount[G3];
__device__ int      g_cellstart[G3];
__device__ int      g_cellfill[G3];
__device__ int      g_cellof[NPTS];
__device__ int      g_sorted[NPTS];
__device__ unsigned g_bmin[3];
__device__ unsigned g_bmax[3];
__device__ int      g_bsum[256];
__device__ int      g_bsum2[256];
__device__ float    g_film[7*512];          // per layer: [gamma(256) | beta(256)]

// monotone float<->uint mapping for atomic min/max
__device__ __forceinline__ unsigned fmap(float x){
    unsigned u = __float_as_uint(x);
    return (u & 0x80000000u) ? ~u : (u | 0x80000000u);
}
__device__ __forceinline__ float funmap(unsigned u){
    return (u & 0x80000000u) ? __uint_as_float(u & 0x7FFFFFFFu) : __uint_as_float(~u);
}

// ---------------- init ----------------
__global__ void k_init(){
    int i = blockIdx.x*blockDim.x + threadIdx.x;
    if (i < G3){ g_cellcount[i]=0; g_cellfill[i]=0; }
    if (i < 3){ g_bmin[i]=0xFFFFFFFFu; g_bmax[i]=0u; }
}

// ---------------- prep: packed points, fourier features, bbox ----------------
__global__ void k_prep(const float* __restrict__ x, const float* __restrict__ B){
    int i = blockIdx.x*blockDim.x + threadIdx.x;
    float x0=x[i*3+0], x1=x[i*3+1], x2=x[i*3+2];
    float xsq = x0*x0 + x1*x1 + x2*x2;
    g_pts[i] = make_float4(x0,x1,x2,xsq);
    #pragma unroll
    for (int s=0;s<3;s++){
        #pragma unroll
        for (int m=0;m<8;m++){
            float p = x0*B[(s*3+0)*8+m] + x1*B[(s*3+1)*8+m] + x2*B[(s*3+2)*8+m];
            float sv, cv; sincosf(p, &sv, &cv);
            g_ff[i*48 + s*8 + m]      = sv;
            g_ff[i*48 + 24 + s*8 + m] = cv;
        }
    }
    float mn0=x0, mn1=x1, mn2=x2, mx0=x0, mx1=x1, mx2=x2;
    #pragma unroll
    for (int o=16;o>0;o>>=1){
        mn0=fminf(mn0,__shfl_down_sync(0xffffffffu,mn0,o));
        mn1=fminf(mn1,__shfl_down_sync(0xffffffffu,mn1,o));
        mn2=fminf(mn2,__shfl_down_sync(0xffffffffu,mn2,o));
        mx0=fmaxf(mx0,__shfl_down_sync(0xffffffffu,mx0,o));
        mx1=fmaxf(mx1,__shfl_down_sync(0xffffffffu,mx1,o));
        mx2=fmaxf(mx2,__shfl_down_sync(0xffffffffu,mx2,o));
    }
    if ((threadIdx.x & 31) == 0){
        atomicMin(&g_bmin[0], fmap(mn0)); atomicMax(&g_bmax[0], fmap(mx0));
        atomicMin(&g_bmin[1], fmap(mn1)); atomicMax(&g_bmax[1], fmap(mx1));
        atomicMin(&g_bmin[2], fmap(mn2)); atomicMax(&g_bmax[2], fmap(mx2));
    }
}

// ---------------- cell assignment ----------------
__global__ void k_cell(){
    int i = blockIdx.x*blockDim.x + threadIdx.x;
    float4 p = g_pts[i];
    float lo0=funmap(g_bmin[0]), lo1=funmap(g_bmin[1]), lo2=funmap(g_bmin[2]);
    float ih0 = (float)GD / (funmap(g_bmax[0]) - lo0);
    float ih1 = (float)GD / (funmap(g_bmax[1]) - lo1);
    float ih2 = (float)GD / (funmap(g_bmax[2]) - lo2);
    int cx = min(GD-1, max(0, (int)floorf((p.x - lo0)*ih0)));
    int cy = min(GD-1, max(0, (int)floorf((p.y - lo1)*ih1)));
    int cz = min(GD-1, max(0, (int)floorf((p.z - lo2)*ih2)));
    int c = (cz*GD + cy)*GD + cx;
    g_cellof[i] = c;
    atomicAdd(&g_cellcount[c], 1);
}

// ---------------- exclusive scan of cell counts (3 stages) ----------------
__global__ void k_scan1(){
    __shared__ int s[1024];
    int gid = blockIdx.x*1024 + threadIdx.x;
    int v = g_cellcount[gid];
    s[threadIdx.x] = v; __syncthreads();
    for (int off=1; off<1024; off<<=1){
        int t = (threadIdx.x >= off) ? s[threadIdx.x-off] : 0;
        __syncthreads();
        s[threadIdx.x] += t;
        __syncthreads();
    }
    g_cellstart[gid] = s[threadIdx.x] - v;
    if (threadIdx.x == 1023) g_bsum[blockIdx.x] = s[1023];
}
__global__ void k_scan2(){
    __shared__ int s[256];
    int v = g_bsum[threadIdx.x];
    s[threadIdx.x] = v; __syncthreads();
    for (int off=1; off<256; off<<=1){
        int t = (threadIdx.x >= off) ? s[threadIdx.x-off] : 0;
        __syncthreads();
        s[threadIdx.x] += t;
        __syncthreads();
    }
    g_bsum2[threadIdx.x] = s[threadIdx.x] - v;
}
__global__ void k_scan3(){
    int gid = blockIdx.x*1024 + threadIdx.x;
    g_cellstart[gid] += g_bsum2[blockIdx.x];
}

// ---------------- scatter into cell-sorted order ----------------
__global__ void k_scatter(){
    int i = blockIdx.x*blockDim.x + threadIdx.x;
    int c = g_cellof[i];
    int pos = g_cellstart[c] + atomicAdd(&g_cellfill[c], 1);
    g_sorted[pos] = i;
}

// ---------------- exact kNN via expanding shells ----------------
__global__ void k_knn(){
    int t = blockIdx.x*blockDim.x + threadIdx.x;
    int i = g_sorted[t];                  // cell-sorted for warp coherence
    float4 q = g_pts[i];
    float lo[3], h[3], ih[3], qc[3];
    qc[0]=q.x; qc[1]=q.y; qc[2]=q.z;
    #pragma unroll
    for (int a=0;a<3;a++){
        lo[a] = funmap(g_bmin[a]);
        float hi = funmap(g_bmax[a]);
        h[a]  = (hi - lo[a]) * (1.0f/GD);
        ih[a] = (float)GD / (hi - lo[a]);
    }
    int cc[3];
    #pragma unroll
    for (int a=0;a<3;a++) cc[a] = min(GD-1, max(0, (int)floorf((qc[a]-lo[a])*ih[a])));

    float bd[KNN]; int bi[KNN];
    #pragma unroll
    for (int k=0;k<KNN;k++){ bd[k]=1e30f; bi[k]=0; }

    float qx2 = -2.0f*q.x, qy2 = -2.0f*q.y, qz2 = -2.0f*q.z;

    auto visit = [&](int cell){
        int s = g_cellstart[cell];
        int e = s + g_cellcount[cell];
        for (int j=s; j<e; j++){
            int p = g_sorted[j];
            float4 w = g_pts[p];
            float sc = fmaf(qx2, w.x, fmaf(qy2, w.y, fmaf(qz2, w.z, q.w + w.w)));
            if (sc < bd[KNN-1] && p != i){
                float d2 = sc; int p2 = p;
                #pragma unroll
                for (int k=0;k<KNN;k++){
                    if (d2 < bd[k]){
                        float td=bd[k]; int tp=bi[k];
                        bd[k]=d2; bi[k]=p2; d2=td; p2=tp;
                    }
                }
            }
        }
    };

    for (int r=0; r<GD; ++r){
        int zl = max(cc[2]-r, 0), zh = min(cc[2]+r, GD-1);
        for (int z=zl; z<=zh; ++z){
            bool ze = (z == cc[2]-r) || (z == cc[2]+r);
            int yl = max(cc[1]-r, 0), yh = min(cc[1]+r, GD-1);
            for (int y=yl; y<=yh; ++y){
                bool ye = (y == cc[1]-r) || (y == cc[1]+r);
                int base = (z*GD + y)*GD;
                if (ze || ye){
                    int xl = max(cc[0]-r, 0), xh = min(cc[0]+r, GD-1);
                    for (int xx=xl; xx<=xh; ++xx) visit(base + xx);
                } else {
                    int x1 = cc[0]-r;        if (x1 >= 0) visit(base + x1);
                    int x2 = cc[0]+r;        if (x2 <= GD-1 && r > 0) visit(base + x2);
                }
            }
        }
        // termination: min distance from q to any unsearched cell
        float dmin = 1e30f;
        #pragma unroll
        for (int a=0;a<3;a++){
            if (cc[a]-r > 0)    dmin = fminf(dmin, qc[a] - (lo[a] + (float)(cc[a]-r)*h[a]));
            if (cc[a]+r < GD-1) dmin = fminf(dmin, (lo[a] + (float)(cc[a]+r+1)*h[a]) - qc[a]);
        }
        if (dmin >= 1e29f) break;                      // whole grid searched
        if (bd[KNN-1] + 1e-4f <= dmin*dmin) break;     // provably done (slack for fp filing)
    }
    #pragma unroll
    for (int k=0;k<KNN;k++) g_knn[i*KNN + k] = bi[k];
}

// ---------------- neighbor mean gather ----------------
__global__ void k_gather(const float* __restrict__ g, float* __restrict__ agg){
    int i = blockIdx.x;
    int j = threadIdx.x;
    __shared__ int idx[KNN];
    if (j < KNN) idx[j] = g_knn[i*KNN + j];
    __syncthreads();
    float s = 0.f;
    #pragma unroll
    for (int k=0;k<KNN;k++) s += g[idx[k]*192 + j];
    agg[i*192 + j] = s * (1.0f/12.0f);
}

// ---------------- FiLM precompute ----------------
__global__ void k_film(const float* __restrict__ cond, const float* __restrict__ Wg,
                       const float* __restrict__ bgf, const float* __restrict__ Wb,
                       const float* __restrict__ bbf){
    int l = blockIdx.x, j = threadIdx.x;
    float ga = bgf[l*256 + j], ba = bbf[l*256 + j];
    for (int k=0;k<64;k++){
        float cv = cond[k];
        ga = fmaf(cv, Wg[(l*64+k)*256 + j], ga);
        ba = fmaf(cv, Wb[(l*64+k)*256 + j], ba);
    }
    g_film[l*512 + j]       = ga;
    g_film[l*512 + 256 + j] = ba;
}

// ---------------- fused GEMM: C = epi(A@B [+ A2@B2] [+bias] [film] [silu] [+res]) ----------------
#define F_BIAS 1
#define F_FILM 2
#define F_SILU 4
#define F_RES  8

template<bool DUAL>
__global__ void __launch_bounds__(256) k_gemm(
    const float* __restrict__ A,  const float* __restrict__ B,
    const float* __restrict__ A2, const float* __restrict__ B2,
    const float* __restrict__ bias, const float* __restrict__ gamma,
    const float* __restrict__ beta, const float* __restrict__ res,
    float* __restrict__ C, int K, int M, int flags)
{
    __shared__ __align__(16) float As [16][64];
    __shared__ __align__(16) float Bs [16][64];
    __shared__ __align__(16) float As2[DUAL?16:1][DUAL?64:1];
    __shared__ __align__(16) float Bs2[DUAL?16:1][DUAL?64:1];

    int tid = threadIdx.x;
    int tx = tid & 15, ty = tid >> 4;
    int row0 = blockIdx.y*64, col0 = blockIdx.x*64;
    int ar = tid >> 2, ak = (tid & 3) * 4;   // A tile load: row ar, k ak..ak+3
    int bk = tid >> 4, bc = (tid & 15) * 4;  // B tile load: k bk, cols bc..bc+3

    float acc[4][4];
    #pragma unroll
    for (int u=0;u<4;u++)
        #pragma unroll
        for (int v=0;v<4;v++) acc[u][v]=0.f;

    for (int k0=0; k0<K; k0+=16){
        float4 av = *(const float4*)&A[(row0+ar)*K + k0 + ak];
        As[ak+0][ar]=av.x; As[ak+1][ar]=av.y; As[ak+2][ar]=av.z; As[ak+3][ar]=av.w;
        *(float4*)&Bs[bk][bc] = *(const float4*)&B[(k0+bk)*M + col0 + bc];
        if (DUAL){
            float4 av2 = *(const float4*)&A2[(row0+ar)*K + k0 + ak];
            As2[ak+0][ar]=av2.x; As2[ak+1][ar]=av2.y; As2[ak+2][ar]=av2.z; As2[ak+3][ar]=av2.w;
            *(float4*)&Bs2[bk][bc] = *(const float4*)&B2[(k0+bk)*M + col0 + bc];
        }
        __syncthreads();
        #pragma unroll
        for (int kk=0; kk<16; kk++){
            float4 a = *(const float4*)&As[kk][ty*4];
            float4 b = *(const float4*)&Bs[kk][tx*4];
            float aa[4]={a.x,a.y,a.z,a.w}, bb[4]={b.x,b.y,b.z,b.w};
            #pragma unroll
            for (int u=0;u<4;u++)
                #pragma unroll
                for (int v=0;v<4;v++) acc[u][v] = fmaf(aa[u], bb[v], acc[u][v]);
            if (DUAL){
                float4 a2 = *(const float4*)&As2[kk][ty*4];
                float4 b2 = *(const float4*)&Bs2[kk][tx*4];
                float aa2[4]={a2.x,a2.y,a2.z,a2.w}, bb2[4]={b2.x,b2.y,b2.z,b2.w};
                #pragma unroll
                for (int u=0;u<4;u++)
                    #pragma unroll
                    for (int v=0;v<4;v++) acc[u][v] = fmaf(aa2[u], bb2[v], acc[u][v]);
            }
        }
        __syncthreads();
    }

    #pragma unroll
    for (int u=0;u<4;u++){
        int rrow = row0 + ty*4 + u;
        #pragma unroll
        for (int v=0;v<4;v++){
            int ccol = col0 + tx*4 + v;
            float val = acc[u][v];
            if (flags & F_BIAS) val += bias[ccol];
            if (flags & F_FILM) val = fmaf(val, 1.f + gamma[ccol], beta[ccol]);
            if (flags & F_SILU) val = val * __fdividef(1.f, 1.f + __expf(-val));
            if (flags & F_RES)  val += res[rrow*M + ccol];
            C[rrow*M + ccol] = val;
        }
    }
}

// ---------------- output projection ----------------
__global__ void k_out(const float* __restrict__ h, const float* __restrict__ Wout,
                      const float* __restrict__ bout, float* __restrict__ out){
    int i = blockIdx.x*blockDim.x + threadIdx.x;
    if (i >= NPTS) return;
    const float* hr = h + i*256;
    float a0=0.f, a1=0.f, a2=0.f;
    #pragma unroll 8
    for (int k=0;k<256;k++){
        float hv = hr[k];
        a0 = fmaf(hv, Wout[k*3+0], a0);
        a1 = fmaf(hv, Wout[k*3+1], a1);
        a2 = fmaf(hv, Wout[k*3+2], a2);
    }
    out[i*3+0] = (a0 + bout[0]) * 0.01f;
    out[i*3+1] = (a1 + bout[1]) * 0.01f;
    out[i*3+2] = (a2 + bout[2]) * 0.01f;
}

// ---------------- launch ----------------
extern "C" void kernel_launch(void* const* d_in, const int* in_sizes, int n_in,
                              void* d_out, int out_size)
{
    const float* x      = (const float*)d_in[0];
    const float* cond   = (const float*)d_in[1];
    const float* B      = (const float*)d_in[2];
    const float* W_in   = (const float*)d_in[3];
    const float* b_in   = (const float*)d_in[4];
    const float* Wg_in  = (const float*)d_in[5];
    const float* bg_in  = (const float*)d_in[6];
    const float* Ws     = (const float*)d_in[7];
    const float* Wn     = (const float*)d_in[8];
    const float* bg     = (const float*)d_in[9];
    const float* Wg_out = (const float*)d_in[10];
    const float* W      = (const float*)d_in[11];
    const float* bmlp   = (const float*)d_in[12];
    const float* Wf_g   = (const float*)d_in[13];
    const float* bf_g   = (const float*)d_in[14];
    const float* Wf_b   = (const float*)d_in[15];
    const float* Wf_b2  = (const float*)d_in[16]; // bf_b
    const float* W_out  = (const float*)d_in[17];
    const float* b_out  = (const float*)d_in[18];
    float* out = (float*)d_out;

    float *p_ff,*p_h0,*p_ga,*p_gb,*p_agg,*p_ha,*p_hb,*p_film;
    cudaGetSymbolAddress((void**)&p_ff,  g_ff);
    cudaGetSymbolAddress((void**)&p_h0,  g_h0);
    cudaGetSymbolAddress((void**)&p_ga,  g_ga);
    cudaGetSymbolAddress((void**)&p_gb,  g_gb);
    cudaGetSymbolAddress((void**)&p_agg, g_agg);
    cudaGetSymbolAddress((void**)&p_ha,  g_ha);
    cudaGetSymbolAddress((void**)&p_hb,  g_hb);
    cudaGetSymbolAddress((void**)&p_film,g_film);

    // graph build
    k_init   <<<G3/256, 256>>>();
    k_prep   <<<NPTS/256, 256>>>(x, B);
    k_cell   <<<NPTS/256, 256>>>();
    k_scan1  <<<256, 1024>>>();
    k_scan2  <<<1, 256>>>();
    k_scan3  <<<256, 1024>>>();
    k_scatter<<<NPTS/256, 256>>>();
    k_knn    <<<NPTS/256, 256>>>();

    // embeddings
    k_gemm<false><<<dim3(4,1024), 256>>>(p_ff, W_in, nullptr, nullptr, b_in,
                                         nullptr, nullptr, nullptr, p_h0, 48, 256, F_BIAS|F_SILU);
    k_gemm<false><<<dim3(3,1024), 256>>>(p_ff, Wg_in, nullptr, nullptr, bg_in,
                                         nullptr, nullptr, nullptr, p_ga, 48, 192, F_BIAS|F_SILU);
    k_film<<<7, 256>>>(cond, Wf_g, bf_g, Wf_b, Wf_b2);

    // graph message passing
    float* gcur = p_ga; float* gnxt = p_gb;
    for (int l=0; l<4; l++){
        k_gather<<<NPTS, 192>>>(gcur, p_agg);
        k_gemm<true><<<dim3(3,1024), 256>>>(gcur, Ws + l*192*192, p_agg, Wn + l*192*192,
                                            bg + l*192, nullptr, nullptr, nullptr,
                                            gnxt, 192, 192, F_BIAS|F_SILU);
        float* t = gcur; gcur = gnxt; gnxt = t;
    }

    // inject graph context: h = h0 + gfeat @ Wg_out
    k_gemm<false><<<dim3(4,1024), 256>>>(gcur, Wg_out, nullptr, nullptr, nullptr,
                                         nullptr, nullptr, p_h0, p_ha, 192, 256, F_RES);

    // FiLM trunk
    float* hcur = p_ha; float* hnxt = p_hb;
    for (int l=0; l<7; l++){
        int flags = F_BIAS|F_FILM|F_SILU;
        const float* res = nullptr;
        if (l == 2 || l == 5){ flags |= F_RES; res = p_h0; }
        k_gemm<false><<<dim3(4,1024), 256>>>(hcur, W + l*256*256, nullptr, nullptr,
                                             bmlp + l*256, p_film + l*512, p_film + l*512 + 256,
                                             res, hnxt, 256, 256, flags);
        float* t = hcur; hcur = hnxt; hnxt = t;
    }

    k_out<<<NPTS/256, 256>>>(hcur, W_out, b_out, out);
}

// round 2
// speedup vs baseline: 1.1251x; 1.1251x over previous
#include <cuda_runtime.h>
#include <math.h>

#define NPTS 65536
#define GD   64
#define G3   (GD*GD*GD)
#define KNN  12

// ---------------- scratch (device globals; no allocation allowed) ----------------
__device__ float4   g_pts[NPTS];            // x,y,z,|x|^2
__device__ float    g_ff[NPTS*48];
__device__ float    g_h0[NPTS*256];
__device__ float    g_ga[NPTS*192];
__device__ float    g_gb[NPTS*192];
__device__ float    g_agg[NPTS*192];
__device__ float    g_ha[NPTS*256];
__device__ float    g_hb[NPTS*256];
__device__ int      g_knn[NPTS*KNN];
__device__ int      g_cellcount[G3];
__device__ int      g_cellstart[G3];
__device__ int      g_cellfill[G3];
__device__ int      g_cellof[NPTS];
__device__ int      g_sorted[NPTS];
__device__ unsigned g_bmin[3];
__device__ unsigned g_bmax[3];
__device__ int      g_bsum[256];
__device__ int      g_bsum2[256];
__device__ float    g_film[7*512];          // per layer: [gamma(256) | beta(256)]

// monotone float<->uint mapping for atomic min/max
__device__ __forceinline__ unsigned fmap(float x){
    unsigned u = __float_as_uint(x);
    return (u & 0x80000000u) ? ~u : (u | 0x80000000u);
}
__device__ __forceinline__ float funmap(unsigned u){
    return (u & 0x80000000u) ? __uint_as_float(u & 0x7FFFFFFFu) : __uint_as_float(~u);
}

// ---------------- packed f32x2 helpers ----------------
__device__ __forceinline__ unsigned long long pack2(float x){
    unsigned long long r;
    asm("mov.b64 %0, {%1, %1};" : "=l"(r) : "f"(x));
    return r;
}
__device__ __forceinline__ void ffma2(unsigned long long& d, unsigned long long a, unsigned long long b){
    asm("fma.rn.f32x2 %0, %1, %2, %0;" : "+l"(d) : "l"(a), "l"(b));
}
__device__ __forceinline__ void unpack2(unsigned long long v, float& lo, float& hi){
    asm("mov.b64 {%0, %1}, %2;" : "=f"(lo), "=f"(hi) : "l"(v));
}

// ---------------- init ----------------
__global__ void k_init(){
    int i = blockIdx.x*blockDim.x + threadIdx.x;
    if (i < G3){ g_cellcount[i]=0; g_cellfill[i]=0; }
    if (i < 3){ g_bmin[i]=0xFFFFFFFFu; g_bmax[i]=0u; }
}

// ---------------- prep: packed points, fourier features, bbox ----------------
__global__ void k_prep(const float* __restrict__ x, const float* __restrict__ B){
    int i = blockIdx.x*blockDim.x + threadIdx.x;
    float x0=x[i*3+0], x1=x[i*3+1], x2=x[i*3+2];
    float xsq = x0*x0 + x1*x1 + x2*x2;
    g_pts[i] = make_float4(x0,x1,x2,xsq);
    #pragma unroll
    for (int s=0;s<3;s++){
        #pragma unroll
        for (int m=0;m<8;m++){
            float p = x0*B[(s*3+0)*8+m] + x1*B[(s*3+1)*8+m] + x2*B[(s*3+2)*8+m];
            float sv, cv; sincosf(p, &sv, &cv);
            g_ff[i*48 + s*8 + m]      = sv;
            g_ff[i*48 + 24 + s*8 + m] = cv;
        }
    }
    float mn0=x0, mn1=x1, mn2=x2, mx0=x0, mx1=x1, mx2=x2;
    #pragma unroll
    for (int o=16;o>0;o>>=1){
        mn0=fminf(mn0,__shfl_down_sync(0xffffffffu,mn0,o));
        mn1=fminf(mn1,__shfl_down_sync(0xffffffffu,mn1,o));
        mn2=fminf(mn2,__shfl_down_sync(0xffffffffu,mn2,o));
        mx0=fmaxf(mx0,__shfl_down_sync(0xffffffffu,mx0,o));
        mx1=fmaxf(mx1,__shfl_down_sync(0xffffffffu,mx1,o));
        mx2=fmaxf(mx2,__shfl_down_sync(0xffffffffu,mx2,o));
    }
    if ((threadIdx.x & 31) == 0){
        atomicMin(&g_bmin[0], fmap(mn0)); atomicMax(&g_bmax[0], fmap(mx0));
        atomicMin(&g_bmin[1], fmap(mn1)); atomicMax(&g_bmax[1], fmap(mx1));
        atomicMin(&g_bmin[2], fmap(mn2)); atomicMax(&g_bmax[2], fmap(mx2));
    }
}

// ---------------- cell assignment ----------------
__global__ void k_cell(){
    int i = blockIdx.x*blockDim.x + threadIdx.x;
    float4 p = g_pts[i];
    float lo0=funmap(g_bmin[0]), lo1=funmap(g_bmin[1]), lo2=funmap(g_bmin[2]);
    float ih0 = (float)GD / (funmap(g_bmax[0]) - lo0);
    float ih1 = (float)GD / (funmap(g_bmax[1]) - lo1);
    float ih2 = (float)GD / (funmap(g_bmax[2]) - lo2);
    int cx = min(GD-1, max(0, (int)floorf((p.x - lo0)*ih0)));
    int cy = min(GD-1, max(0, (int)floorf((p.y - lo1)*ih1)));
    int cz = min(GD-1, max(0, (int)floorf((p.z - lo2)*ih2)));
    int c = (cz*GD + cy)*GD + cx;
    g_cellof[i] = c;
    atomicAdd(&g_cellcount[c], 1);
}

// ---------------- exclusive scan of cell counts (3 stages) ----------------
__global__ void k_scan1(){
    __shared__ int s[1024];
    int gid = blockIdx.x*1024 + threadIdx.x;
    int v = g_cellcount[gid];
    s[threadIdx.x] = v; __syncthreads();
    for (int off=1; off<1024; off<<=1){
        int t = (threadIdx.x >= off) ? s[threadIdx.x-off] : 0;
        __syncthreads();
        s[threadIdx.x] += t;
        __syncthreads();
    }
    g_cellstart[gid] = s[threadIdx.x] - v;
    if (threadIdx.x == 1023) g_bsum[blockIdx.x] = s[1023];
}
__global__ void k_scan2(){
    __shared__ int s[256];
    int v = g_bsum[threadIdx.x];
    s[threadIdx.x] = v; __syncthreads();
    for (int off=1; off<256; off<<=1){
        int t = (threadIdx.x >= off) ? s[threadIdx.x-off] : 0;
        __syncthreads();
        s[threadIdx.x] += t;
        __syncthreads();
    }
    g_bsum2[threadIdx.x] = s[threadIdx.x] - v;
}
__global__ void k_scan3(){
    int gid = blockIdx.x*1024 + threadIdx.x;
    g_cellstart[gid] += g_bsum2[blockIdx.x];
}

// ---------------- scatter into cell-sorted order ----------------
__global__ void k_scatter(){
    int i = blockIdx.x*blockDim.x + threadIdx.x;
    int c = g_cellof[i];
    int pos = g_cellstart[c] + atomicAdd(&g_cellfill[c], 1);
    g_sorted[pos] = i;
}

// ---------------- exact kNN via expanding shells ----------------
__global__ void k_knn(){
    int t = blockIdx.x*blockDim.x + threadIdx.x;
    int i = g_sorted[t];                  // cell-sorted for warp coherence
    float4 q = g_pts[i];
    float lo[3], h[3], ih[3], qc[3];
    qc[0]=q.x; qc[1]=q.y; qc[2]=q.z;
    #pragma unroll
    for (int a=0;a<3;a++){
        lo[a] = funmap(g_bmin[a]);
        float hi = funmap(g_bmax[a]);
        h[a]  = (hi - lo[a]) * (1.0f/GD);
        ih[a] = (float)GD / (hi - lo[a]);
    }
    int cc[3];
    #pragma unroll
    for (int a=0;a<3;a++) cc[a] = min(GD-1, max(0, (int)floorf((qc[a]-lo[a])*ih[a])));

    float bd[KNN]; int bi[KNN];
    #pragma unroll
    for (int k=0;k<KNN;k++){ bd[k]=1e30f; bi[k]=0; }

    float qx2 = -2.0f*q.x, qy2 = -2.0f*q.y, qz2 = -2.0f*q.z;

    auto visit = [&](int cell){
        int s = g_cellstart[cell];
        int e = s + g_cellcount[cell];
        for (int j=s; j<e; j++){
            int p = g_sorted[j];
            float4 w = g_pts[p];
            float sc = fmaf(qx2, w.x, fmaf(qy2, w.y, fmaf(qz2, w.z, q.w + w.w)));
            if (sc < bd[KNN-1] && p != i){
                float d2 = sc; int p2 = p;
                #pragma unroll
                for (int k=0;k<KNN;k++){
                    if (d2 < bd[k]){
                        float td=bd[k]; int tp=bi[k];
                        bd[k]=d2; bi[k]=p2; d2=td; p2=tp;
                    }
                }
            }
        }
    };

    for (int r=0; r<GD; ++r){
        int zl = max(cc[2]-r, 0), zh = min(cc[2]+r, GD-1);
        for (int z=zl; z<=zh; ++z){
            bool ze = (z == cc[2]-r) || (z == cc[2]+r);
            int yl = max(cc[1]-r, 0), yh = min(cc[1]+r, GD-1);
            for (int y=yl; y<=yh; ++y){
                bool ye = (y == cc[1]-r) || (y == cc[1]+r);
                int base = (z*GD + y)*GD;
                if (ze || ye){
                    int xl = max(cc[0]-r, 0), xh = min(cc[0]+r, GD-1);
                    for (int xx=xl; xx<=xh; ++xx) visit(base + xx);
                } else {
                    int x1 = cc[0]-r;        if (x1 >= 0) visit(base + x1);
                    int x2 = cc[0]+r;        if (x2 <= GD-1 && r > 0) visit(base + x2);
                }
            }
        }
        // termination: min distance from q to any unsearched cell
        float dmin = 1e30f;
        #pragma unroll
        for (int a=0;a<3;a++){
            if (cc[a]-r > 0)    dmin = fminf(dmin, qc[a] - (lo[a] + (float)(cc[a]-r)*h[a]));
            if (cc[a]+r < GD-1) dmin = fminf(dmin, (lo[a] + (float)(cc[a]+r+1)*h[a]) - qc[a]);
        }
        if (dmin >= 1e29f) break;                      // whole grid searched
        if (bd[KNN-1] + 1e-4f <= dmin*dmin) break;     // provably done (slack for fp filing)
    }
    #pragma unroll
    for (int k=0;k<KNN;k++) g_knn[i*KNN + k] = bi[k];
}

// ---------------- neighbor mean gather (warp per node, coalesced) ----------------
__global__ void k_gather(const float* __restrict__ g, float* __restrict__ agg){
    int gt   = blockIdx.x*blockDim.x + threadIdx.x;
    int node = gt >> 5;
    int lane = threadIdx.x & 31;
    int idx = 0;
    if (lane < KNN) idx = g_knn[node*KNN + lane];
    float s[6] = {0.f,0.f,0.f,0.f,0.f,0.f};
    #pragma unroll
    for (int k=0;k<KNN;k++){
        int j = __shfl_sync(0xffffffffu, idx, k);
        const float* row = g + (size_t)j*192;
        #pragma unroll
        for (int c=0;c<6;c++) s[c] += row[lane + 32*c];
    }
    float* o = agg + (size_t)node*192;
    #pragma unroll
    for (int c=0;c<6;c++) o[lane + 32*c] = s[c] * (1.0f/12.0f);
}

// ---------------- FiLM precompute ----------------
__global__ void k_film(const float* __restrict__ cond, const float* __restrict__ Wg,
                       const float* __restrict__ bgf, const float* __restrict__ Wb,
                       const float* __restrict__ bbf){
    int l = blockIdx.x, j = threadIdx.x;
    float ga = bgf[l*256 + j], ba = bbf[l*256 + j];
    for (int k=0;k<64;k++){
        float cv = cond[k];
        ga = fmaf(cv, Wg[(l*64+k)*256 + j], ga);
        ba = fmaf(cv, Wb[(l*64+k)*256 + j], ba);
    }
    g_film[l*512 + j]       = ga;
    g_film[l*512 + 256 + j] = ba;
}

// ---------------- fused GEMM (FFMA2): C = epi(A@B [+ A2@B2] [+bias] [film] [silu] [+res]) --------
#define F_BIAS 1
#define F_FILM 2
#define F_SILU 4
#define F_RES  8

// 128x64 tile, BK=16, 256 threads, 8 rows x 4 cols per thread (row-pairs packed f32x2)
template<bool DUAL>
__global__ void __launch_bounds__(256,2) k_gemm(
    const float* __restrict__ A,  const float* __restrict__ B,
    const float* __restrict__ A2, const float* __restrict__ B2,
    const float* __restrict__ bias, const float* __restrict__ gamma,
    const float* __restrict__ beta, const float* __restrict__ res,
    float* __restrict__ C, int K, int M, int flags)
{
    __shared__ __align__(16) float As[2][16][128];
    __shared__ __align__(16) float Bs[2][16][64];

    const int tid  = threadIdx.x;
    const int tx   = tid & 15;            // col group (4 cols)
    const int ty   = tid >> 4;            // row group (8 rows)
    const int row0 = blockIdx.y*128;
    const int col0 = blockIdx.x*64;

    const int arow = tid >> 1;            // A-load row within tile
    const int ak   = (tid & 1) * 8;       // A-load k offset (8 floats)
    const int bk   = tid >> 4;            // B-load k row
    const int bc   = (tid & 15) * 4;      // B-load col offset

    const int ktiles = K >> 4;
    const int T = DUAL ? (2*ktiles) : ktiles;

    unsigned long long acc[4][4];
    #pragma unroll
    for (int u=0;u<4;u++)
        #pragma unroll
        for (int v=0;v<4;v++) acc[u][v] = 0ull;

    float4 ra0, ra1, rb;

    // --- load tile t into regs ---
    auto ldt = [&](int t){
        const float* Ab = A; const float* Bb = B; int tt = t;
        if (DUAL && t >= ktiles){ Ab = A2; Bb = B2; tt = t - ktiles; }
        int k0 = tt << 4;
        const float* ap = &Ab[(size_t)(row0+arow)*K + k0 + ak];
        ra0 = *(const float4*)(ap);
        ra1 = *(const float4*)(ap+4);
        rb  = *(const float4*)&Bb[(size_t)(k0+bk)*M + col0 + bc];
    };
    // --- store regs into smem buffer ---
    auto stt = [&](int buf){
        As[buf][ak+0][arow]=ra0.x; As[buf][ak+1][arow]=ra0.y;
        As[buf][ak+2][arow]=ra0.z; As[buf][ak+3][arow]=ra0.w;
        As[buf][ak+4][arow]=ra1.x; As[buf][ak+5][arow]=ra1.y;
        As[buf][ak+6][arow]=ra1.z; As[buf][ak+7][arow]=ra1.w;
        *(float4*)&Bs[buf][bk][bc] = rb;
    };

    ldt(0); stt(0); __syncthreads();

    for (int t=0; t<T; t++){
        int cur = t & 1;
        if (t+1 < T) ldt(t+1);
        #pragma unroll
        for (int kk=0; kk<16; kk++){
            const float* ar = &As[cur][kk][ty*8];
            ulonglong2 q0 = *(const ulonglong2*)(ar);
            ulonglong2 q1 = *(const ulonglong2*)(ar+4);
            float4 bv = *(const float4*)&Bs[cur][kk][tx*4];
            unsigned long long bb0 = pack2(bv.x), bb1 = pack2(bv.y),
                               bb2 = pack2(bv.z), bb3 = pack2(bv.w);
            ffma2(acc[0][0], q0.x, bb0); ffma2(acc[0][1], q0.x, bb1);
            ffma2(acc[0][2], q0.x, bb2); ffma2(acc[0][3], q0.x, bb3);
            ffma2(acc[1][0], q0.y, bb0); ffma2(acc[1][1], q0.y, bb1);
            ffma2(acc[1][2], q0.y, bb2); ffma2(acc[1][3], q0.y, bb3);
            ffma2(acc[2][0], q1.x, bb0); ffma2(acc[2][1], q1.x, bb1);
            ffma2(acc[2][2], q1.x, bb2); ffma2(acc[2][3], q1.x, bb3);
            ffma2(acc[3][0], q1.y, bb0); ffma2(acc[3][1], q1.y, bb1);
            ffma2(acc[3][2], q1.y, bb2); ffma2(acc[3][3], q1.y, bb3);
        }
        if (t+1 < T){ stt(cur^1); __syncthreads(); }
    }

    // --- epilogue ---
    int colb = col0 + tx*4;
    float4 bi4 = make_float4(0,0,0,0), gm4 = make_float4(0,0,0,0), bt4 = make_float4(0,0,0,0);
    if (flags & F_BIAS) bi4 = *(const float4*)&bias[colb];
    if (flags & F_FILM){ gm4 = *(const float4*)&gamma[colb]; bt4 = *(const float4*)&beta[colb]; }
    float bia[4] = {bi4.x,bi4.y,bi4.z,bi4.w};
    float gma[4] = {gm4.x,gm4.y,gm4.z,gm4.w};
    float bta[4] = {bt4.x,bt4.y,bt4.z,bt4.w};

    #pragma unroll
    for (int rp=0; rp<4; rp++){
        float vlo[4], vhi[4];
        #pragma unroll
        for (int v=0; v<4; v++) unpack2(acc[rp][v], vlo[v], vhi[v]);
        #pragma unroll
        for (int half=0; half<2; half++){
            float* vv = half ? vhi : vlo;
            int row = row0 + ty*8 + rp*2 + half;
            float4 rr = make_float4(0,0,0,0);
            if (flags & F_RES) rr = *(const float4*)&res[(size_t)row*M + colb];
            float rra[4] = {rr.x, rr.y, rr.z, rr.w};
            float o[4];
            #pragma unroll
            for (int v=0; v<4; v++){
                float val = vv[v];
                if (flags & F_BIAS) val += bia[v];
                if (flags & F_FILM) val = fmaf(val, 1.f + gma[v], bta[v]);
                if (flags & F_SILU) val = val * __fdividef(1.f, 1.f + __expf(-val));
                if (flags & F_RES)  val += rra[v];
                o[v] = val;
            }
            *(float4*)&C[(size_t)row*M + colb] = make_float4(o[0],o[1],o[2],o[3]);
        }
    }
}

// ---------------- output projection ----------------
__global__ void k_out(const float* __restrict__ h, const float* __restrict__ Wout,
                      const float* __restrict__ bout, float* __restrict__ out){
    int i = blockIdx.x*blockDim.x + threadIdx.x;
    if (i >= NPTS) return;
    const float* hr = h + (size_t)i*256;
    float a0=0.f, a1=0.f, a2=0.f;
    #pragma unroll 8
    for (int k=0;k<256;k++){
        float hv = hr[k];
        a0 = fmaf(hv, Wout[k*3+0], a0);
        a1 = fmaf(hv, Wout[k*3+1], a1);
        a2 = fmaf(hv, Wout[k*3+2], a2);
    }
    out[i*3+0] = (a0 + bout[0]) * 0.01f;
    out[i*3+1] = (a1 + bout[1]) * 0.01f;
    out[i*3+2] = (a2 + bout[2]) * 0.01f;
}

// ---------------- launch ----------------
extern "C" void kernel_launch(void* const* d_in, const int* in_sizes, int n_in,
                              void* d_out, int out_size)
{
    const float* x      = (const float*)d_in[0];
    const float* cond   = (const float*)d_in[1];
    const float* B      = (const float*)d_in[2];
    const float* W_in   = (const float*)d_in[3];
    const float* b_in   = (const float*)d_in[4];
    const float* Wg_in  = (const float*)d_in[5];
    const float* bg_in  = (const float*)d_in[6];
    const float* Ws     = (const float*)d_in[7];
    const float* Wn     = (const float*)d_in[8];
    const float* bg     = (const float*)d_in[9];
    const float* Wg_out = (const float*)d_in[10];
    const float* W      = (const float*)d_in[11];
    const float* bmlp   = (const float*)d_in[12];
    const float* Wf_g   = (const float*)d_in[13];
    const float* bf_g   = (const float*)d_in[14];
    const float* Wf_b   = (const float*)d_in[15];
    const float* bf_b   = (const float*)d_in[16];
    const float* W_out  = (const float*)d_in[17];
    const float* b_out  = (const float*)d_in[18];
    float* out = (float*)d_out;

    float *p_ff,*p_h0,*p_ga,*p_gb,*p_agg,*p_ha,*p_hb,*p_film;
    cudaGetSymbolAddress((void**)&p_ff,  g_ff);
    cudaGetSymbolAddress((void**)&p_h0,  g_h0);
    cudaGetSymbolAddress((void**)&p_ga,  g_ga);
    cudaGetSymbolAddress((void**)&p_gb,  g_gb);
    cudaGetSymbolAddress((void**)&p_agg, g_agg);
    cudaGetSymbolAddress((void**)&p_ha,  g_ha);
    cudaGetSymbolAddress((void**)&p_hb,  g_hb);
    cudaGetSymbolAddress((void**)&p_film,g_film);

    // graph build
    k_init   <<<G3/256, 256>>>();
    k_prep   <<<NPTS/256, 256>>>(x, B);
    k_cell   <<<NPTS/256, 256>>>();
    k_scan1  <<<256, 1024>>>();
    k_scan2  <<<1, 256>>>();
    k_scan3  <<<256, 1024>>>();
    k_scatter<<<NPTS/256, 256>>>();
    k_knn    <<<NPTS/256, 256>>>();

    // embeddings
    k_gemm<false><<<dim3(4,512), 256>>>(p_ff, W_in, nullptr, nullptr, b_in,
                                        nullptr, nullptr, nullptr, p_h0, 48, 256, F_BIAS|F_SILU);
    k_gemm<false><<<dim3(3,512), 256>>>(p_ff, Wg_in, nullptr, nullptr, bg_in,
                                        nullptr, nullptr, nullptr, p_ga, 48, 192, F_BIAS|F_SILU);
    k_film<<<7, 256>>>(cond, Wf_g, bf_g, Wf_b, bf_b);

    // graph message passing
    float* gcur = p_ga; float* gnxt = p_gb;
    for (int l=0; l<4; l++){
        k_gather<<<NPTS*32/256, 256>>>(gcur, p_agg);
        k_gemm<true><<<dim3(3,512), 256>>>(gcur, Ws + l*192*192, p_agg, Wn + l*192*192,
                                           bg + l*192, nullptr, nullptr, nullptr,
                                           gnxt, 192, 192, F_BIAS|F_SILU);
        float* t = gcur; gcur = gnxt; gnxt = t;
    }

    // inject graph context: h = h0 + gfeat @ Wg_out
    k_gemm<false><<<dim3(4,512), 256>>>(gcur, Wg_out, nullptr, nullptr, nullptr,
                                        nullptr, nullptr, p_h0, p_ha, 192, 256, F_RES);

    // FiLM trunk
    float* hcur = p_ha; float* hnxt = p_hb;
    for (int l=0; l<7; l++){
        int flags = F_BIAS|F_FILM|F_SILU;
        const float* res = nullptr;
        if (l == 2 || l == 5){ flags |= F_RES; res = p_h0; }
        k_gemm<false><<<dim3(4,512), 256>>>(hcur, W + l*256*256, nullptr, nullptr,
                                            bmlp + l*256, p_film + l*512, p_film + l*512 + 256,
                                            res, hnxt, 256, 256, flags);
        float* t = hcur; hcur = hnxt; hnxt = t;
    }

    k_out<<<NPTS/256, 256>>>(hcur, W_out, b_out, out);
}

// round 4
// speedup vs baseline: 1.2093x; 1.0749x over previous
#include <cuda_runtime.h>
#include <cuda_bf16.h>
#include <cstdint>
#include <math.h>

#define NPTS 65536
#define GD   64
#define G3   (GD*GD*GD)
#define KNN  12

// ================= mma.sync helpers (family-agnostic HMMA path) =================
__device__ __forceinline__ uint32_t smem_to_u32(const void* p){
    uint32_t a;
    asm("{ .reg .u64 t; cvta.to.shared.u64 t, %1; cvt.u32.u64 %0, t; }" : "=r"(a) : "l"(p));
    return a;
}
__device__ __forceinline__ void ldsm4(uint32_t& r0,uint32_t& r1,uint32_t& r2,uint32_t& r3,uint32_t addr){
    asm volatile("ldmatrix.sync.aligned.m8n8.x4.shared.b16 {%0,%1,%2,%3},[%4];"
        : "=r"(r0),"=r"(r1),"=r"(r2),"=r"(r3) : "r"(addr));
}
__device__ __forceinline__ void ldsm2(uint32_t& r0,uint32_t& r1,uint32_t addr){
    asm volatile("ldmatrix.sync.aligned.m8n8.x2.shared.b16 {%0,%1},[%2];"
        : "=r"(r0),"=r"(r1) : "r"(addr));
}
__device__ __forceinline__ void mma16816(float* c, const uint32_t* a, const uint32_t* b){
    asm volatile("mma.sync.aligned.m16n8k16.row.col.f32.bf16.bf16.f32 "
        "{%0,%1,%2,%3},{%4,%5,%6,%7},{%8,%9},{%0,%1,%2,%3};"
        : "+f"(c[0]),"+f"(c[1]),"+f"(c[2]),"+f"(c[3])
        : "r"(a[0]),"r"(a[1]),"r"(a[2]),"r"(a[3]), "r"(b[0]),"r"(b[1]));
}

// ================= scratch =================
__device__ float4        g_pts[NPTS];
__device__ float4        g_spts[NPTS];          // cell-sorted
__device__ int           g_sorted[NPTS];        // pos -> orig
__device__ int           g_knn[NPTS*KNN];       // sorted-space indices
__device__ int           g_cellcount[G3];
__device__ int           g_cellstart[G3];
__device__ int           g_cellfill[G3];
__device__ int           g_cellof[NPTS];
__device__ unsigned      g_bmin[3];
__device__ unsigned      g_bmax[3];
__device__ int           g_bsum[256];
__device__ int           g_bsum2[256];
__device__ float         g_film[7*512];
__device__ __nv_bfloat16 g_ffh[NPTS*64],  g_ffl[NPTS*64];
__device__ __nv_bfloat16 g_gah[NPTS*192], g_gal[NPTS*192];
__device__ __nv_bfloat16 g_gbh[NPTS*192], g_gbl[NPTS*192];
__device__ __nv_bfloat16 g_aggh[NPTS*192],g_aggl[NPTS*192];
__device__ __nv_bfloat16 g_hah[NPTS*256], g_hal[NPTS*256];
__device__ __nv_bfloat16 g_hbh[NPTS*256], g_hbl[NPTS*256];
__device__ float         g_h0[NPTS*256];
__device__ float         g_hf[NPTS*256];

__device__ __forceinline__ unsigned fmap(float x){
    unsigned u = __float_as_uint(x);
    return (u & 0x80000000u) ? ~u : (u | 0x80000000u);
}
__device__ __forceinline__ float funmap(unsigned u){
    return (u & 0x80000000u) ? __uint_as_float(u & 0x7FFFFFFFu) : __uint_as_float(~u);
}

// ================= graph build =================
__global__ void k_init(){
    int i = blockIdx.x*blockDim.x + threadIdx.x;
    if (i < G3){ g_cellcount[i]=0; g_cellfill[i]=0; }
    if (i < 3){ g_bmin[i]=0xFFFFFFFFu; g_bmax[i]=0u; }
}

__global__ void k_prep(const float* __restrict__ x){
    int i = blockIdx.x*blockDim.x + threadIdx.x;
    float x0=x[i*3+0], x1=x[i*3+1], x2=x[i*3+2];
    g_pts[i] = make_float4(x0,x1,x2, x0*x0+x1*x1+x2*x2);
    float mn0=x0, mn1=x1, mn2=x2, mx0=x0, mx1=x1, mx2=x2;
    #pragma unroll
    for (int o=16;o>0;o>>=1){
        mn0=fminf(mn0,__shfl_down_sync(0xffffffffu,mn0,o));
        mn1=fminf(mn1,__shfl_down_sync(0xffffffffu,mn1,o));
        mn2=fminf(mn2,__shfl_down_sync(0xffffffffu,mn2,o));
        mx0=fmaxf(mx0,__shfl_down_sync(0xffffffffu,mx0,o));
        mx1=fmaxf(mx1,__shfl_down_sync(0xffffffffu,mx1,o));
        mx2=fmaxf(mx2,__shfl_down_sync(0xffffffffu,mx2,o));
    }
    if ((threadIdx.x & 31) == 0){
        atomicMin(&g_bmin[0], fmap(mn0)); atomicMax(&g_bmax[0], fmap(mx0));
        atomicMin(&g_bmin[1], fmap(mn1)); atomicMax(&g_bmax[1], fmap(mx1));
        atomicMin(&g_bmin[2], fmap(mn2)); atomicMax(&g_bmax[2], fmap(mx2));
    }
}

__global__ void k_cell(){
    int i = blockIdx.x*blockDim.x + threadIdx.x;
    float4 p = g_pts[i];
    float lo0=funmap(g_bmin[0]), lo1=funmap(g_bmin[1]), lo2=funmap(g_bmin[2]);
    float ih0 = (float)GD / (funmap(g_bmax[0]) - lo0);
    float ih1 = (float)GD / (funmap(g_bmax[1]) - lo1);
    float ih2 = (float)GD / (funmap(g_bmax[2]) - lo2);
    int cx = min(GD-1, max(0, (int)floorf((p.x - lo0)*ih0)));
    int cy = min(GD-1, max(0, (int)floorf((p.y - lo1)*ih1)));
    int cz = min(GD-1, max(0, (int)floorf((p.z - lo2)*ih2)));
    int c = (cz*GD + cy)*GD + cx;
    g_cellof[i] = c;
    atomicAdd(&g_cellcount[c], 1);
}

__global__ void k_scan1(){
    __shared__ int s[1024];
    int gid = blockIdx.x*1024 + threadIdx.x;
    int v = g_cellcount[gid];
    s[threadIdx.x] = v; __syncthreads();
    for (int off=1; off<1024; off<<=1){
        int t = (threadIdx.x >= off) ? s[threadIdx.x-off] : 0;
        __syncthreads(); s[threadIdx.x] += t; __syncthreads();
    }
    g_cellstart[gid] = s[threadIdx.x] - v;
    if (threadIdx.x == 1023) g_bsum[blockIdx.x] = s[1023];
}
__global__ void k_scan2(){
    __shared__ int s[256];
    int v = g_bsum[threadIdx.x];
    s[threadIdx.x] = v; __syncthreads();
    for (int off=1; off<256; off<<=1){
        int t = (threadIdx.x >= off) ? s[threadIdx.x-off] : 0;
        __syncthreads(); s[threadIdx.x] += t; __syncthreads();
    }
    g_bsum2[threadIdx.x] = s[threadIdx.x] - v;
}
__global__ void k_scan3(){
    int gid = blockIdx.x*1024 + threadIdx.x;
    g_cellstart[gid] += g_bsum2[blockIdx.x];
}

__global__ void k_scatter(){
    int i = blockIdx.x*blockDim.x + threadIdx.x;
    int c = g_cellof[i];
    int pos = g_cellstart[c] + atomicAdd(&g_cellfill[c], 1);
    g_sorted[pos] = i;
    g_spts[pos]  = g_pts[i];
}

// fourier features in sorted order -> bf16 hi/lo, padded to 64 cols
__global__ void k_ff(const float* __restrict__ B){
    int i = blockIdx.x*blockDim.x + threadIdx.x;
    float4 p = g_spts[i];
    float f[48];
    #pragma unroll
    for (int s=0;s<3;s++){
        #pragma unroll
        for (int m=0;m<8;m++){
            float pr = p.x*B[(s*3+0)*8+m] + p.y*B[(s*3+1)*8+m] + p.z*B[(s*3+2)*8+m];
            float sv, cv; sincosf(pr, &sv, &cv);
            f[s*8+m] = sv; f[24+s*8+m] = cv;
        }
    }
    #pragma unroll
    for (int c=0;c<48;c++){
        float v = f[c];
        __nv_bfloat16 hv = __float2bfloat16(v);
        g_ffh[i*64+c] = hv;
        g_ffl[i*64+c] = __float2bfloat16(v - __bfloat162float(hv));
    }
    #pragma unroll
    for (int c=48;c<64;c++){
        g_ffh[i*64+c] = __float2bfloat16(0.f);
        g_ffl[i*64+c] = __float2bfloat16(0.f);
    }
}

// exact kNN via expanding shells (sorted space, contiguous candidates)
__global__ void k_knn(){
    int i = blockIdx.x*blockDim.x + threadIdx.x;   // sorted position
    float4 q = g_spts[i];
    float lo[3], h[3], ih[3], qc[3];
    qc[0]=q.x; qc[1]=q.y; qc[2]=q.z;
    #pragma unroll
    for (int a=0;a<3;a++){
        lo[a] = funmap(g_bmin[a]);
        float hi = funmap(g_bmax[a]);
        h[a]  = (hi - lo[a]) * (1.0f/GD);
        ih[a] = (float)GD / (hi - lo[a]);
    }
    int cc[3];
    #pragma unroll
    for (int a=0;a<3;a++) cc[a] = min(GD-1, max(0, (int)floorf((qc[a]-lo[a])*ih[a])));

    float bd[KNN]; int bi[KNN];
    #pragma unroll
    for (int k=0;k<KNN;k++){ bd[k]=1e30f; bi[k]=0; }
    float qx2 = -2.0f*q.x, qy2 = -2.0f*q.y, qz2 = -2.0f*q.z;

    auto visit = [&](int cell){
        int s = g_cellstart[cell];
        int e = s + g_cellcount[cell];
        for (int j=s; j<e; j++){
            float4 w = g_spts[j];
            float sc = fmaf(qx2, w.x, fmaf(qy2, w.y, fmaf(qz2, w.z, q.w + w.w)));
            if (sc < bd[KNN-1] && j != i){
                float d2 = sc; int p2 = j;
                #pragma unroll
                for (int k=0;k<KNN;k++){
                    if (d2 < bd[k]){
                        float td=bd[k]; int tp=bi[k];
                        bd[k]=d2; bi[k]=p2; d2=td; p2=tp;
                    }
                }
            }
        }
    };

    for (int r=0; r<GD; ++r){
        int zl = max(cc[2]-r, 0), zh = min(cc[2]+r, GD-1);
        for (int z=zl; z<=zh; ++z){
            bool ze = (z == cc[2]-r) || (z == cc[2]+r);
            int yl = max(cc[1]-r, 0), yh = min(cc[1]+r, GD-1);
            for (int y=yl; y<=yh; ++y){
                bool ye = (y == cc[1]-r) || (y == cc[1]+r);
                int base = (z*GD + y)*GD;
                if (ze || ye){
                    int xl = max(cc[0]-r, 0), xh = min(cc[0]+r, GD-1);
                    for (int xx=xl; xx<=xh; ++xx) visit(base + xx);
                } else {
                    int x1 = cc[0]-r; if (x1 >= 0) visit(base + x1);
                    int x2 = cc[0]+r; if (x2 <= GD-1 && r > 0) visit(base + x2);
                }
            }
        }
        float dmin = 1e30f;
        #pragma unroll
        for (int a=0;a<3;a++){
            if (cc[a]-r > 0)    dmin = fminf(dmin, qc[a] - (lo[a] + (float)(cc[a]-r)*h[a]));
            if (cc[a]+r < GD-1) dmin = fminf(dmin, (lo[a] + (float)(cc[a]+r+1)*h[a]) - qc[a]);
        }
        if (dmin >= 1e29f) break;
        if (bd[KNN-1] + 1e-4f <= dmin*dmin) break;
    }
    #pragma unroll
    for (int k=0;k<KNN;k++) g_knn[i*KNN + k] = bi[k];
}

// neighbor mean gather (bf16 pairs in/out), warp per node
__global__ void k_gather(const __nv_bfloat16* __restrict__ gh, const __nv_bfloat16* __restrict__ gl,
                         __nv_bfloat16* __restrict__ oh, __nv_bfloat16* __restrict__ ol){
    int gt   = blockIdx.x*blockDim.x + threadIdx.x;
    int node = gt >> 5;
    int lane = threadIdx.x & 31;
    int idx = 0;
    if (lane < KNN) idx = g_knn[node*KNN + lane];
    float s[6] = {0.f,0.f,0.f,0.f,0.f,0.f};
    #pragma unroll
    for (int k=0;k<KNN;k++){
        int j = __shfl_sync(0xffffffffu, idx, k);
        size_t base = (size_t)j*192;
        #pragma unroll
        for (int c=0;c<6;c++){
            int col = lane + 32*c;
            s[c] += __bfloat162float(gh[base+col]) + __bfloat162float(gl[base+col]);
        }
    }
    size_t ob = (size_t)node*192;
    #pragma unroll
    for (int c=0;c<6;c++){
        float v = s[c] * (1.0f/12.0f);
        int col = lane + 32*c;
        __nv_bfloat16 hv = __float2bfloat16(v);
        oh[ob+col] = hv;
        ol[ob+col] = __float2bfloat16(v - __bfloat162float(hv));
    }
}

__global__ void k_film(const float* __restrict__ cond, const float* __restrict__ Wg,
                       const float* __restrict__ bgf, const float* __restrict__ Wb,
                       const float* __restrict__ bbf){
    int l = blockIdx.x, j = threadIdx.x;
    float ga = bgf[l*256 + j], ba = bbf[l*256 + j];
    for (int k=0;k<64;k++){
        float cv = cond[k];
        ga = fmaf(cv, Wg[(l*64+k)*256 + j], ga);
        ba = fmaf(cv, Wb[(l*64+k)*256 + j], ba);
    }
    g_film[l*512 + j]       = ga;
    g_film[l*512 + 256 + j] = ba;
}

// ================= HMMA bf16x3 GEMM =================
#define F_BIAS 1
#define F_FILM 2
#define F_SILU 4
#define F_RES  8
#define F_F32  16
#define F_BF16 32

// 128x64 block tile, 8 warps (4 m x 2 n), 32x32 per warp, BK=32.
// A = [seg1 | seg2] concatenated along K; weights fp32 split to bf16 hi/lo on the fly.
__global__ void __launch_bounds__(256) k_mma(
    const __nv_bfloat16* __restrict__ a1h, const __nv_bfloat16* __restrict__ a1l,
    const float* __restrict__ W1, int kspan1, int kvalid1,
    const __nv_bfloat16* __restrict__ a2h, const __nv_bfloat16* __restrict__ a2l,
    const float* __restrict__ W2, int kspan2,
    int Mout,
    const float* __restrict__ bias, const float* __restrict__ gamma,
    const float* __restrict__ beta, const float* __restrict__ resi,
    float* __restrict__ outf, __nv_bfloat16* __restrict__ outh, __nv_bfloat16* __restrict__ outl,
    int flags)
{
    __shared__ __nv_bfloat16 Ah[128][40], Al[128][40], Bh[64][40], Bl[64][40];

    int tid = threadIdx.x, wid = tid>>5, lane = tid&31;
    int wm = wid & 3, wn = wid >> 2;              // 4 x 2 warp grid
    int row0 = blockIdx.y*128, col0 = blockIdx.x*64;

    float acc[2][4][4];
    #pragma unroll
    for (int mt=0;mt<2;mt++)
        #pragma unroll
        for (int nt=0;nt<4;nt++)
            #pragma unroll
            for (int e=0;e<4;e++) acc[mt][nt][e]=0.f;

    // ldmatrix smem addresses (per lane, fixed across chunks)
    uint32_t aAh = smem_to_u32(&Ah[wm*32 + (lane & 15)][(lane >> 4) * 8]);
    uint32_t aAl = smem_to_u32(&Al[wm*32 + (lane & 15)][(lane >> 4) * 8]);
    uint32_t aBh = smem_to_u32(&Bh[wn*32 + (lane & 7)][((lane >> 3) & 1) * 8]);
    uint32_t aBl = smem_to_u32(&Bl[wn*32 + (lane & 7)][((lane >> 3) & 1) * 8]);

    int nchunk = (kspan1 + kspan2) >> 5;
    for (int c=0; c<nchunk; c++){
        int kg = c<<5;
        const __nv_bfloat16 *ah, *al; const float* Wp; int span, kv, koff;
        if (kg < kspan1){ ah=a1h; al=a1l; Wp=W1; span=kspan1; kv=kvalid1; koff=kg; }
        else            { ah=a2h; al=a2l; Wp=W2; span=kspan2; kv=kspan2; koff=kg-kspan1; }

        // A tiles: 128 rows x 32 bf16 (hi & lo); 8B vector loads
        for (int t=tid; t<1024; t+=256){
            int r = t>>3, g = (t&7)*4;
            size_t s = (size_t)(row0+r)*span + koff + g;
            *(uint2*)&Ah[r][g] = *(const uint2*)(ah + s);
            *(uint2*)&Al[r][g] = *(const uint2*)(al + s);
        }
        // B tiles: 64 n-rows x 32 k, split fp32 weights; coalesced over n
        for (int t=tid; t<2048; t+=256){
            int n = t & 63, kk = t >> 6;
            int k0 = koff + kk;
            float w = (k0 < kv) ? Wp[(size_t)k0*Mout + col0 + n] : 0.f;
            __nv_bfloat16 hb = __float2bfloat16(w);
            Bh[n][kk] = hb;
            Bl[n][kk] = __float2bfloat16(w - __bfloat162float(hb));
        }
        __syncthreads();

        #pragma unroll
        for (int ks=0; ks<2; ks++){
            uint32_t afh[2][4], afl[2][4], bfh[4][2], bfl[4][2];
            #pragma unroll
            for (int mt=0; mt<2; mt++){
                uint32_t off = (mt*16*40 + ks*16) * 2;   // bytes
                ldsm4(afh[mt][0],afh[mt][1],afh[mt][2],afh[mt][3], aAh + off);
                ldsm4(afl[mt][0],afl[mt][1],afl[mt][2],afl[mt][3], aAl + off);
            }
            #pragma unroll
            for (int nt=0; nt<4; nt++){
                uint32_t off = (nt*8*40 + ks*16) * 2;
                ldsm2(bfh[nt][0],bfh[nt][1], aBh + off);
                ldsm2(bfl[nt][0],bfl[nt][1], aBl + off);
            }
            #pragma unroll
            for (int mt=0; mt<2; mt++)
                #pragma unroll
                for (int nt=0; nt<4; nt++){
                    mma16816(acc[mt][nt], afh[mt], bfh[nt]);
                    mma16816(acc[mt][nt], afh[mt], bfl[nt]);
                    mma16816(acc[mt][nt], afl[mt], bfh[nt]);
                }
        }
        __syncthreads();
    }

    // ---- epilogue: C frag layout m16n8 -> rows lane/4 (+8), cols 2*(lane%4) ----
    #pragma unroll
    for (int mt=0; mt<2; mt++){
        #pragma unroll
        for (int nt=0; nt<4; nt++){
            int colb = col0 + wn*32 + nt*8 + 2*(lane & 3);
            #pragma unroll
            for (int half=0; half<2; half++){
                int row = row0 + wm*32 + mt*16 + (lane >> 2) + half*8;
                float v0 = acc[mt][nt][half*2+0];
                float v1 = acc[mt][nt][half*2+1];
                if (flags & F_BIAS){ v0 += bias[colb]; v1 += bias[colb+1]; }
                if (flags & F_FILM){
                    v0 = fmaf(v0, 1.f + gamma[colb],   beta[colb]);
                    v1 = fmaf(v1, 1.f + gamma[colb+1], beta[colb+1]);
                }
                if (flags & F_SILU){
                    v0 = v0 * __fdividef(1.f, 1.f + __expf(-v0));
                    v1 = v1 * __fdividef(1.f, 1.f + __expf(-v1));
                }
                size_t o = (size_t)row*Mout + colb;
                if (flags & F_RES){ v0 += resi[o]; v1 += resi[o+1]; }
                if (flags & F_F32){ *(float2*)&outf[o] = make_float2(v0, v1); }
                if (flags & F_BF16){
                    __nv_bfloat16 h0 = __float2bfloat16(v0), h1 = __float2bfloat16(v1);
                    *(__nv_bfloat162*)&outh[o] = __halves2bfloat162(h0, h1);
                    *(__nv_bfloat162*)&outl[o] = __halves2bfloat162(
                        __float2bfloat16(v0 - __bfloat162float(h0)),
                        __float2bfloat16(v1 - __bfloat162float(h1)));
                }
            }
        }
    }
}

// ================= output projection =================
__global__ void k_out(const float* __restrict__ h, const float* __restrict__ Wout,
                      const float* __restrict__ bout, float* __restrict__ out){
    int i = blockIdx.x*blockDim.x + threadIdx.x;
    if (i >= NPTS) return;
    const float* hr = h + (size_t)i*256;
    float a0=0.f, a1=0.f, a2=0.f;
    #pragma unroll 8
    for (int k=0;k<256;k++){
        float hv = hr[k];
        a0 = fmaf(hv, Wout[k*3+0], a0);
        a1 = fmaf(hv, Wout[k*3+1], a1);
        a2 = fmaf(hv, Wout[k*3+2], a2);
    }
    int orig = g_sorted[i];
    out[orig*3+0] = (a0 + bout[0]) * 0.01f;
    out[orig*3+1] = (a1 + bout[1]) * 0.01f;
    out[orig*3+2] = (a2 + bout[2]) * 0.01f;
}

// ================= launch =================
extern "C" void kernel_launch(void* const* d_in, const int* in_sizes, int n_in,
                              void* d_out, int out_size)
{
    const float* x      = (const float*)d_in[0];
    const float* cond   = (const float*)d_in[1];
    const float* B      = (const float*)d_in[2];
    const float* W_in   = (const float*)d_in[3];
    const float* b_in   = (const float*)d_in[4];
    const float* Wg_in  = (const float*)d_in[5];
    const float* bg_in  = (const float*)d_in[6];
    const float* Ws     = (const float*)d_in[7];
    const float* Wn     = (const float*)d_in[8];
    const float* bg     = (const float*)d_in[9];
    const float* Wg_out = (const float*)d_in[10];
    const float* W      = (const float*)d_in[11];
    const float* bmlp   = (const float*)d_in[12];
    const float* Wf_g   = (const float*)d_in[13];
    const float* bf_g   = (const float*)d_in[14];
    const float* Wf_b   = (const float*)d_in[15];
    const float* bf_b   = (const float*)d_in[16];
    const float* W_out  = (const float*)d_in[17];
    const float* b_out  = (const float*)d_in[18];
    float* out = (float*)d_out;

    float *p_h0,*p_hf,*p_film;
    __nv_bfloat16 *p_ffh,*p_ffl,*p_gah,*p_gal,*p_gbh,*p_gbl,*p_aggh,*p_aggl,*p_hah,*p_hal,*p_hbh,*p_hbl;
    cudaGetSymbolAddress((void**)&p_h0,  g_h0);
    cudaGetSymbolAddress((void**)&p_hf,  g_hf);
    cudaGetSymbolAddress((void**)&p_film,g_film);
    cudaGetSymbolAddress((void**)&p_ffh, g_ffh);  cudaGetSymbolAddress((void**)&p_ffl, g_ffl);
    cudaGetSymbolAddress((void**)&p_gah, g_gah);  cudaGetSymbolAddress((void**)&p_gal, g_gal);
    cudaGetSymbolAddress((void**)&p_gbh, g_gbh);  cudaGetSymbolAddress((void**)&p_gbl, g_gbl);
    cudaGetSymbolAddress((void**)&p_aggh,g_aggh); cudaGetSymbolAddress((void**)&p_aggl,g_aggl);
    cudaGetSymbolAddress((void**)&p_hah, g_hah);  cudaGetSymbolAddress((void**)&p_hal, g_hal);
    cudaGetSymbolAddress((void**)&p_hbh, g_hbh);  cudaGetSymbolAddress((void**)&p_hbl, g_hbl);

    // graph build (sorted space)
    k_init   <<<G3/256, 256>>>();
    k_prep   <<<NPTS/256, 256>>>(x);
    k_cell   <<<NPTS/256, 256>>>();
    k_scan1  <<<256, 1024>>>();
    k_scan2  <<<1, 256>>>();
    k_scan3  <<<256, 1024>>>();
    k_scatter<<<NPTS/256, 256>>>();
    k_ff     <<<NPTS/256, 256>>>(B);
    k_knn    <<<NPTS/256, 256>>>();
    k_film   <<<7, 256>>>(cond, Wf_g, bf_g, Wf_b, bf_b);

    // h0 = silu(ff @ W_in + b_in)   (fp32, used for residuals)
    k_mma<<<dim3(4,512), 256>>>(p_ffh, p_ffl, W_in, 64, 48,
        nullptr, nullptr, nullptr, 0, 256,
        b_in, nullptr, nullptr, nullptr, p_h0, nullptr, nullptr, F_BIAS|F_SILU|F_F32);
    // gfeat = silu(ff @ Wg_in + bg_in)
    k_mma<<<dim3(3,512), 256>>>(p_ffh, p_ffl, Wg_in, 64, 48,
        nullptr, nullptr, nullptr, 0, 192,
        bg_in, nullptr, nullptr, nullptr, nullptr, p_gah, p_gal, F_BIAS|F_SILU|F_BF16);

    // graph message passing
    __nv_bfloat16 *gch=p_gah, *gcl=p_gal, *gnh=p_gbh, *gnl=p_gbl;
    for (int l=0; l<4; l++){
        k_gather<<<NPTS*32/256, 256>>>(gch, gcl, p_aggh, p_aggl);
        k_mma<<<dim3(3,512), 256>>>(gch, gcl, Ws + l*192*192, 192, 192,
            p_aggh, p_aggl, Wn + l*192*192, 192, 192,
            bg + l*192, nullptr, nullptr, nullptr, nullptr, gnh, gnl, F_BIAS|F_SILU|F_BF16);
        __nv_bfloat16* t;
        t=gch; gch=gnh; gnh=t;  t=gcl; gcl=gnl; gnl=t;
    }

    // h = h0 + gfeat @ Wg_out
    k_mma<<<dim3(4,512), 256>>>(gch, gcl, Wg_out, 192, 192,
        nullptr, nullptr, nullptr, 0, 256,
        nullptr, nullptr, nullptr, p_h0, nullptr, p_hah, p_hal, F_RES|F_BF16);

    // FiLM trunk
    __nv_bfloat16 *hch=p_hah, *hcl=p_hal, *hnh=p_hbh, *hnl=p_hbl;
    for (int l=0; l<7; l++){
        int flags = F_BIAS|F_FILM|F_SILU;
        const float* res = nullptr;
        if (l == 2 || l == 5){ flags |= F_RES; res = p_h0; }
        float* of = nullptr;
        __nv_bfloat16 *oh = hnh, *ol = hnl;
        if (l == 6){ flags |= F_F32; of = p_hf; oh = nullptr; ol = nullptr; }
        else flags |= F_BF16;
        k_mma<<<dim3(4,512), 256>>>(hch, hcl, W + l*256*256, 256, 256,
            nullptr, nullptr, nullptr, 0, 256,
            bmlp + l*256, p_film + l*512, p_film + l*512 + 256,
            res, of, oh, ol, flags);
        __nv_bfloat16* t;
        t=hch; hch=hnh; hnh=t;  t=hcl; hcl=hnl; hnl=t;
    }

    k_out<<<NPTS/256, 256>>>(p_hf, W_out, b_out, out);
}